// round 1
// baseline (speedup 1.0000x reference)
#include <cuda_runtime.h>
#include <stdint.h>

#define NPTS   262144
#define GRIDE  256
#define TSIZE  (256*256*256)
#define NK     26          // off-center taps (k=13 handled densely)
#define BM     128         // center-gemm point tile

// ---------------- scratch (device globals: allowed; no allocations) -------
__device__ int  g_table[TSIZE];        // stores idx+1, 0 = empty (64 MB)
__device__ int  g_counts[NK];
__device__ int2 g_pairs[NK * NPTS];    // per-k segments (i, j)

// ---------------- f32x2 helpers -------------------------------------------
__device__ __forceinline__ unsigned long long ffma2(unsigned long long a,
                                                    unsigned long long b,
                                                    unsigned long long c) {
    unsigned long long d;
    asm("fma.rn.f32x2 %0, %1, %2, %3;" : "=l"(d) : "l"(a), "l"(b), "l"(c));
    return d;
}
__device__ __forceinline__ unsigned long long pack2(float lo, float hi) {
    unsigned long long r;
    asm("mov.b64 %0, {%1, %2};" : "=l"(r) : "f"(lo), "f"(hi));
    return r;
}
__device__ __forceinline__ void unpack2(unsigned long long v, float& lo, float& hi) {
    asm("mov.b64 {%0, %1}, %2;" : "=f"(lo), "=f"(hi) : "l"(v));
}

// ---------------- 1) clear touched cells + counters -----------------------
__global__ __launch_bounds__(256) void k_clear(const int* __restrict__ coords) {
    int i = blockIdx.x * 256 + threadIdx.x;
    if (blockIdx.x == 0 && threadIdx.x < NK) g_counts[threadIdx.x] = 0;
    int x = coords[3*i], y = coords[3*i+1], z = coords[3*i+2];
    g_table[(x * GRIDE + y) * GRIDE + z] = 0;
}

// ---------------- 2) insert (max index wins = last-write-wins) ------------
__global__ __launch_bounds__(256) void k_insert(const int* __restrict__ coords) {
    int i = blockIdx.x * 256 + threadIdx.x;
    int x = coords[3*i], y = coords[3*i+1], z = coords[3*i+2];
    atomicMax(&g_table[(x * GRIDE + y) * GRIDE + z], i + 1);
}

// ---------------- 3) probe 26 off-center taps, build rulebook -------------
__global__ __launch_bounds__(256) void k_probe(const int* __restrict__ coords) {
    int i = blockIdx.x * 256 + threadIdx.x;
    int x = coords[3*i], y = coords[3*i+1], z = coords[3*i+2];
    int lane = threadIdx.x & 31;
    int j[NK];
    #pragma unroll
    for (int kk = 0; kk < NK; kk++) {
        int k  = kk + (kk >= 13);
        int nx = x + k / 9 - 1;
        int ny = y + (k / 3) % 3 - 1;
        int nz = z + k % 3 - 1;
        bool inb = ((unsigned)nx < 256u) && ((unsigned)ny < 256u) && ((unsigned)nz < 256u);
        j[kk] = inb ? g_table[(nx * GRIDE + ny) * GRIDE + nz] : 0;
    }
    #pragma unroll
    for (int kk = 0; kk < NK; kk++) {
        bool valid = j[kk] > 0;
        unsigned m = __ballot_sync(0xffffffffu, valid);
        if (!m) continue;
        int leader = __ffs(m) - 1;
        int pos = 0;
        if (lane == leader) pos = atomicAdd(&g_counts[kk], __popc(m));
        pos = __shfl_sync(0xffffffffu, pos, leader);
        if (valid) {
            int mypos = pos + __popc(m & ((1u << lane) - 1u));
            g_pairs[kk * NPTS + mypos] = make_int2(i, j[kk] - 1);
        }
    }
}

// ---------------- 4) center tap (k=13): dense gathered GEMM ---------------
// smem: [0,32K) WS2 = W13 duplicated f32x2; [32K,64K) FS = feats^T [ci][m];
//       [64K,64K+512) JJ
__global__ __launch_bounds__(256) void k_center(const int* __restrict__ coords,
                                                const float* __restrict__ feats,
                                                const float* __restrict__ kw,
                                                float* __restrict__ out) {
    extern __shared__ unsigned char smraw[];
    unsigned long long* WS2 = (unsigned long long*)smraw;
    float*              FS  = (float*)(smraw + 32768);
    int*                JJ  = (int*)(smraw + 65536);

    int tid  = threadIdx.x;
    int base = blockIdx.x * BM;

    const float* W = kw + 13 * 64 * 64;
    for (int e = tid; e < 4096; e += 256) {
        float w = W[e];
        WS2[e] = pack2(w, w);
    }
    if (tid < BM) {
        int i = base + tid;
        int lin = (coords[3*i] * GRIDE + coords[3*i+1]) * GRIDE + coords[3*i+2];
        JJ[tid] = g_table[lin] - 1;   // always occupied (self)
    }
    __syncthreads();

    // gather feats rows, store transposed FS[ci][m]
    for (int idx = tid; idx < BM * 16; idx += 256) {
        int m  = idx & (BM - 1);
        int cq = idx >> 7;            // 0..15
        float4 v = *(const float4*)(feats + (size_t)JJ[m] * 64 + cq * 4);
        FS[(cq*4 + 0) * BM + m] = v.x;
        FS[(cq*4 + 1) * BM + m] = v.y;
        FS[(cq*4 + 2) * BM + m] = v.z;
        FS[(cq*4 + 3) * BM + m] = v.w;
    }
    __syncthreads();

    int tx = tid & 15, ty = tid >> 4;
    int tm = ty * 8, tn = tx * 4;     // 8 points x 4 couts per thread

    unsigned long long acc[4][4];
    #pragma unroll
    for (int p = 0; p < 4; p++)
        #pragma unroll
        for (int n = 0; n < 4; n++) acc[p][n] = 0ULL;

    #pragma unroll
    for (int ci = 0; ci < 64; ci++) {
        ulonglong2 a01 = *(const ulonglong2*)(FS + ci * BM + tm);
        ulonglong2 a23 = *(const ulonglong2*)(FS + ci * BM + tm + 4);
        ulonglong2 w01 = *(const ulonglong2*)(WS2 + ci * 64 + tn);
        ulonglong2 w23 = *(const ulonglong2*)(WS2 + ci * 64 + tn + 2);
        unsigned long long ap[4] = {a01.x, a01.y, a23.x, a23.y};
        unsigned long long wp[4] = {w01.x, w01.y, w23.x, w23.y};
        #pragma unroll
        for (int p = 0; p < 4; p++)
            #pragma unroll
            for (int n = 0; n < 4; n++)
                acc[p][n] = ffma2(ap[p], wp[n], acc[p][n]);
    }

    #pragma unroll
    for (int p = 0; p < 4; p++) {
        float lo[4], hi[4];
        #pragma unroll
        for (int n = 0; n < 4; n++) unpack2(acc[p][n], lo[n], hi[n]);
        int i0 = base + tm + 2 * p;
        *(float4*)(out + (size_t)i0       * 64 + tn) = make_float4(lo[0], lo[1], lo[2], lo[3]);
        *(float4*)(out + (size_t)(i0 + 1) * 64 + tn) = make_float4(hi[0], hi[1], hi[2], hi[3]);
    }
}

// ---------------- 5) off-center taps: per-k batched matvec + atomicAdd ----
__global__ __launch_bounds__(256) void k_pairs(const float* __restrict__ feats,
                                               const float* __restrict__ kw,
                                               float* __restrict__ out) {
    __shared__ float WS[4096];                    // W_k [ci][co]
    __shared__ unsigned long long RB[8][64];      // duplicated feats row per warp

    int kk  = blockIdx.x;
    int cnt = g_counts[kk];
    if ((int)(blockIdx.y * 8) >= cnt) return;     // uniform
    int k   = kk + (kk >= 13);
    int tid = threadIdx.x;

    for (int e = tid; e < 1024; e += 256)
        ((float4*)WS)[e] = ((const float4*)(kw + k * 4096))[e];
    __syncthreads();

    int warp = tid >> 5, lane = tid & 31;
    for (int base = blockIdx.y * 8; base < cnt; base += gridDim.y * 8) {
        int p = base + warp;
        if (p < cnt) {                            // warp-uniform predicate
            int2 pr = g_pairs[kk * NPTS + p];
            float2 f2 = *(const float2*)(feats + (size_t)pr.y * 64 + 2 * lane);
            RB[warp][2*lane]     = pack2(f2.x, f2.x);
            RB[warp][2*lane + 1] = pack2(f2.y, f2.y);
            __syncwarp();
            unsigned long long acc = 0ULL;
            #pragma unroll
            for (int ci = 0; ci < 64; ci++) {
                unsigned long long w = *(const unsigned long long*)(WS + ci * 64 + 2 * lane);
                acc = ffma2(RB[warp][ci], w, acc);
            }
            float r0, r1;
            unpack2(acc, r0, r1);
            atomicAdd(out + (size_t)pr.x * 64 + 2 * lane,     r0);
            atomicAdd(out + (size_t)pr.x * 64 + 2 * lane + 1, r1);
            __syncwarp();                         // protect RB before next fill
        }
    }
}

// ---------------- launch ---------------------------------------------------
extern "C" void kernel_launch(void* const* d_in, const int* in_sizes, int n_in,
                              void* d_out, int out_size) {
    const int*   coords = (const int*)d_in[0];
    const float* feats  = (const float*)d_in[1];
    const float* kw     = (const float*)d_in[2];
    float*       out    = (float*)d_out;

    cudaFuncSetAttribute(k_center, cudaFuncAttributeMaxDynamicSharedMemorySize, 66048);

    k_clear <<<NPTS / 256, 256>>>(coords);
    k_insert<<<NPTS / 256, 256>>>(coords);
    k_probe <<<NPTS / 256, 256>>>(coords);
    k_center<<<NPTS / BM, 256, 66048>>>(coords, feats, kw, out);
    k_pairs <<<dim3(NK, 64), 256>>>(feats, kw, out);
}

// round 2
// speedup vs baseline: 1.1182x; 1.1182x over previous
#include <cuda_runtime.h>
#include <stdint.h>

#define NPTS   262144
#define GRIDE  256
#define TSIZE  (256*256*256)
#define NK     26          // off-center taps (k=13 handled densely)
#define BM     128         // gemm point/pair tile
#define MAXT   40          // y-grid tiles for pairs kernel (grid-stride safe)

typedef unsigned long long ull;

// ---------------- scratch (device globals) --------------------------------
__device__ int  g_table[TSIZE];        // stores idx+1, 0 = empty
__device__ int  g_counts[NK];
__device__ int2 g_pairs[NK * NPTS];    // per-k segments (i, j)

// ---------------- f32x2 helpers -------------------------------------------
__device__ __forceinline__ ull ffma2(ull a, ull b, ull c) {
    ull d;
    asm("fma.rn.f32x2 %0, %1, %2, %3;" : "=l"(d) : "l"(a), "l"(b), "l"(c));
    return d;
}
__device__ __forceinline__ ull pack2(float lo, float hi) {
    ull r;
    asm("mov.b64 %0, {%1, %2};" : "=l"(r) : "f"(lo), "f"(hi));
    return r;
}
__device__ __forceinline__ void unpack2(ull v, float& lo, float& hi) {
    asm("mov.b64 {%0, %1}, %2;" : "=f"(lo), "=f"(hi) : "l"(v));
}

// ---------------- smem layout (bytes) -------------------------------------
// WS2: [64 ci][8 n-chunks][10 ull]  (8 dup-W couts + 2 pad) = 40960 B
//      lane stride across tx = 80B -> start banks {0,20,8,28,16,4,24,12}: conflict-free
// FS : [64 ci][16 m-chunks][12 f32] (8 feats + 4 pad)       = 49152 B
//      lane stride across ty = 48B -> consecutive-4 ty conflict-free
#define SM_WS2  0
#define SM_FS   40960
#define SM_JJ   90112
#define SM_II   90624
#define SM_TOT  91648

// ---------------- 1) clear touched cells + counters -----------------------
__global__ __launch_bounds__(256) void k_clear(const int* __restrict__ coords) {
    int i = blockIdx.x * 256 + threadIdx.x;
    if (blockIdx.x == 0 && threadIdx.x < NK) g_counts[threadIdx.x] = 0;
    int x = coords[3*i], y = coords[3*i+1], z = coords[3*i+2];
    g_table[(x * GRIDE + y) * GRIDE + z] = 0;
}

// ---------------- 2) insert (max index wins = last-write-wins) ------------
__global__ __launch_bounds__(256) void k_insert(const int* __restrict__ coords) {
    int i = blockIdx.x * 256 + threadIdx.x;
    int x = coords[3*i], y = coords[3*i+1], z = coords[3*i+2];
    atomicMax(&g_table[(x * GRIDE + y) * GRIDE + z], i + 1);
}

// ---------------- 3) probe 26 off-center taps, build rulebook -------------
__global__ __launch_bounds__(256) void k_probe(const int* __restrict__ coords) {
    int i = blockIdx.x * 256 + threadIdx.x;
    int x = coords[3*i], y = coords[3*i+1], z = coords[3*i+2];
    int lane = threadIdx.x & 31;
    int j[NK];
    #pragma unroll
    for (int kk = 0; kk < NK; kk++) {
        int k  = kk + (kk >= 13);
        int nx = x + k / 9 - 1;
        int ny = y + (k / 3) % 3 - 1;
        int nz = z + k % 3 - 1;
        bool inb = ((unsigned)nx < 256u) && ((unsigned)ny < 256u) && ((unsigned)nz < 256u);
        j[kk] = inb ? g_table[(nx * GRIDE + ny) * GRIDE + nz] : 0;
    }
    #pragma unroll
    for (int kk = 0; kk < NK; kk++) {
        bool valid = j[kk] > 0;
        unsigned m = __ballot_sync(0xffffffffu, valid);
        if (!m) continue;
        int leader = __ffs(m) - 1;
        int pos = 0;
        if (lane == leader) pos = atomicAdd(&g_counts[kk], __popc(m));
        pos = __shfl_sync(0xffffffffu, pos, leader);
        if (valid) {
            int mypos = pos + __popc(m & ((1u << lane) - 1u));
            g_pairs[kk * NPTS + mypos] = make_int2(i, j[kk] - 1);
        }
    }
}

// ---------------- shared GEMM pieces --------------------------------------
__device__ __forceinline__ void load_w_dup(ull* WS2, const float* __restrict__ Wk, int tid) {
    for (int e = tid; e < 4096; e += 128) {
        float w = Wk[e];
        int ci = e >> 6, co = e & 63;
        WS2[ci * 80 + (co >> 3) * 10 + (co & 7)] = pack2(w, w);
    }
}

__device__ __forceinline__ void gather_fs(float* FS, const int* JJ,
                                          const float* __restrict__ feats, int tid) {
    for (int idx = tid; idx < BM * 16; idx += 128) {
        int m  = idx & (BM - 1);
        int cq = idx >> 7;                        // 0..15
        float4 v = *(const float4*)(feats + (size_t)JJ[m] * 64 + cq * 4);
        int mb = (m >> 3) * 12 + (m & 7);
        FS[(cq * 4 + 0) * 192 + mb] = v.x;
        FS[(cq * 4 + 1) * 192 + mb] = v.y;
        FS[(cq * 4 + 2) * 192 + mb] = v.z;
        FS[(cq * 4 + 3) * 192 + mb] = v.w;
    }
}

// compute acc[4][8]: m-pairs (f32x2) x 8 couts
__device__ __forceinline__ void gemm_core(ull acc[4][8], const float* FS,
                                          const ull* WS2, int tx, int ty) {
    #pragma unroll 8
    for (int ci = 0; ci < 64; ci++) {
        const ulonglong2* apad = (const ulonglong2*)(FS + ci * 192 + ty * 12);
        ulonglong2 a0 = apad[0], a1 = apad[1];
        const ulonglong2* wpad = (const ulonglong2*)(WS2 + ci * 80 + tx * 10);
        ulonglong2 w0 = wpad[0], w1 = wpad[1], w2 = wpad[2], w3 = wpad[3];
        ull ap[4] = {a0.x, a0.y, a1.x, a1.y};
        ull wp[8] = {w0.x, w0.y, w1.x, w1.y, w2.x, w2.y, w3.x, w3.y};
        #pragma unroll
        for (int p = 0; p < 4; p++)
            #pragma unroll
            for (int n = 0; n < 8; n++)
                acc[p][n] = ffma2(ap[p], wp[n], acc[p][n]);
    }
}

// ---------------- 4) center tap (k=13): dense gathered GEMM ---------------
__global__ __launch_bounds__(128) void k_center(const int* __restrict__ coords,
                                                const float* __restrict__ feats,
                                                const float* __restrict__ kw,
                                                float* __restrict__ out) {
    extern __shared__ unsigned char sm[];
    ull*   WS2 = (ull*)(sm + SM_WS2);
    float* FS  = (float*)(sm + SM_FS);
    int*   JJ  = (int*)(sm + SM_JJ);

    int tid  = threadIdx.x;
    int base = blockIdx.x * BM;

    load_w_dup(WS2, kw + 13 * 4096, tid);
    if (tid < BM) {
        int i = base + tid;
        int lin = (coords[3*i] * GRIDE + coords[3*i+1]) * GRIDE + coords[3*i+2];
        JJ[tid] = g_table[lin] - 1;               // always occupied (self)
    }
    __syncthreads();
    gather_fs(FS, JJ, feats, tid);
    __syncthreads();

    int tx = tid & 7, ty = tid >> 3;              // tx: 8 n-chunks, ty: 16 m-chunks
    ull acc[4][8];
    #pragma unroll
    for (int p = 0; p < 4; p++)
        #pragma unroll
        for (int n = 0; n < 8; n++) acc[p][n] = 0ULL;

    gemm_core(acc, FS, WS2, tx, ty);

    #pragma unroll
    for (int p = 0; p < 4; p++) {
        float lo[8], hi[8];
        #pragma unroll
        for (int n = 0; n < 8; n++) unpack2(acc[p][n], lo[n], hi[n]);
        int i0 = base + ty * 8 + 2 * p;
        float* o0 = out + (size_t)i0 * 64 + tx * 8;
        *(float4*)(o0)     = make_float4(lo[0], lo[1], lo[2], lo[3]);
        *(float4*)(o0 + 4) = make_float4(lo[4], lo[5], lo[6], lo[7]);
        float* o1 = o0 + 64;
        *(float4*)(o1)     = make_float4(hi[0], hi[1], hi[2], hi[3]);
        *(float4*)(o1 + 4) = make_float4(hi[4], hi[5], hi[6], hi[7]);
    }
}

// ---------------- 5) off-center taps: tiled GEMM + atomic scatter ---------
__global__ __launch_bounds__(128) void k_pairs(const float* __restrict__ feats,
                                               const float* __restrict__ kw,
                                               float* __restrict__ out) {
    int kk  = blockIdx.x;
    int cnt = g_counts[kk];
    if ((int)(blockIdx.y * BM) >= cnt) return;    // uniform early-exit
    int k   = kk + (kk >= 13);
    int tid = threadIdx.x;

    extern __shared__ unsigned char sm[];
    ull*   WS2 = (ull*)(sm + SM_WS2);
    float* FS  = (float*)(sm + SM_FS);
    int*   JJ  = (int*)(sm + SM_JJ);
    int*   II  = (int*)(sm + SM_II);

    load_w_dup(WS2, kw + k * 4096, tid);

    int tx = tid & 7, ty = tid >> 3;

    for (int t = blockIdx.y; t * BM < cnt; t += MAXT) {
        int tb = t * BM;
        __syncthreads();                          // smem safe to overwrite
        if (tid < BM) {
            int p = tb + tid;
            if (p < cnt) {
                int2 pr = g_pairs[kk * NPTS + p];
                JJ[tid] = pr.y;
                II[tid] = pr.x;
            } else {
                JJ[tid] = 0;
                II[tid] = -1;
            }
        }
        __syncthreads();
        gather_fs(FS, JJ, feats, tid);
        __syncthreads();

        ull acc[4][8];
        #pragma unroll
        for (int p = 0; p < 4; p++)
            #pragma unroll
            for (int n = 0; n < 8; n++) acc[p][n] = 0ULL;

        gemm_core(acc, FS, WS2, tx, ty);

        #pragma unroll
        for (int p = 0; p < 4; p++) {
            float lo[8], hi[8];
            #pragma unroll
            for (int n = 0; n < 8; n++) unpack2(acc[p][n], lo[n], hi[n]);
            int m0 = ty * 8 + 2 * p;
            int i0 = II[m0];
            if (i0 >= 0) {
                float* o = out + (size_t)i0 * 64 + tx * 8;
                #pragma unroll
                for (int n = 0; n < 8; n++) atomicAdd(o + n, lo[n]);
            }
            int i1 = II[m0 + 1];
            if (i1 >= 0) {
                float* o = out + (size_t)i1 * 64 + tx * 8;
                #pragma unroll
                for (int n = 0; n < 8; n++) atomicAdd(o + n, hi[n]);
            }
        }
    }
}

// ---------------- launch ---------------------------------------------------
extern "C" void kernel_launch(void* const* d_in, const int* in_sizes, int n_in,
                              void* d_out, int out_size) {
    const int*   coords = (const int*)d_in[0];
    const float* feats  = (const float*)d_in[1];
    const float* kw     = (const float*)d_in[2];
    float*       out    = (float*)d_out;

    cudaFuncSetAttribute(k_center, cudaFuncAttributeMaxDynamicSharedMemorySize, SM_TOT);
    cudaFuncSetAttribute(k_pairs,  cudaFuncAttributeMaxDynamicSharedMemorySize, SM_TOT);

    k_clear <<<NPTS / 256, 256>>>(coords);
    k_insert<<<NPTS / 256, 256>>>(coords);
    k_probe <<<NPTS / 256, 256>>>(coords);
    k_center<<<NPTS / BM, 128, SM_TOT>>>(coords, feats, kw, out);
    k_pairs <<<dim3(NK, MAXT), 128, SM_TOT>>>(feats, kw, out);
}